// round 12
// baseline (speedup 1.0000x reference)
#include <cuda_runtime.h>
#include <cuda_bf16.h>
#include <mma.h>
#include <math.h>

using namespace nvcuda;

#define NMAX 50000
#define EMAX 800000
#define HID  32
#define DIN  128

// ---------------- scratch (static; no cudaMalloc allowed) ----------------
__device__ __align__(128) __nv_bfloat16 g_y1b[NMAX * HID];   // x @ W1_l.T (bf16)
__device__ __align__(128) __nv_bfloat16 g_agg1b[NMAX * HID]; // bf16 edge sums
__device__ __align__(128) float g_r1[NMAX * HID];            // x @ W1_r.T (fp32)
__device__ __align__(128) float g_deg[NMAX];
__device__ __align__(128) float g_z2[NMAX];
__device__ __align__(128) float g_r2[NMAX];
__device__ __align__(128) float g_agg2[NMAX];
__device__ int g_is64;

// ---------------- helpers ----------------
__device__ __forceinline__ unsigned long long fma2(unsigned long long a,
                                                   unsigned long long b,
                                                   unsigned long long c) {
    unsigned long long d;
    asm("fma.rn.f32x2 %0, %1, %2, %3;" : "=l"(d) : "l"(a), "l"(b), "l"(c));
    return d;
}
__device__ __forceinline__ float hsum2(unsigned long long a) {
    float lo, hi;
    asm("mov.b64 {%0, %1}, %2;" : "=f"(lo), "=f"(hi) : "l"(a));
    return lo + hi;
}
// 16-byte reduction of 8 bf16 values
__device__ __forceinline__ void red_add_bf16x8(void* addr, uint4 v) {
#if !defined(__CUDA_ARCH__) || __CUDA_ARCH__ >= 900
    asm volatile("red.global.add.noftz.v4.bf16x2 [%0], {%1, %2, %3, %4};"
                 :: "l"(addr), "r"(v.x), "r"(v.y), "r"(v.z), "r"(v.w)
                 : "memory");
#else
    __nv_bfloat162* p = (__nv_bfloat162*)addr;
    atomicAdd(p + 0, *(__nv_bfloat162*)&v.x);
    atomicAdd(p + 1, *(__nv_bfloat162*)&v.y);
    atomicAdd(p + 2, *(__nv_bfloat162*)&v.z);
    atomicAdd(p + 3, *(__nv_bfloat162*)&v.w);
#endif
}
__device__ __forceinline__ void load_edges4(const void* ei, int E, int e0,
                                            int is64, int* s, int* d) {
    if (is64) {
        longlong4 sv = *(const longlong4*)((const long long*)ei + e0);
        longlong4 dv = *(const longlong4*)((const long long*)ei + E + e0);
        s[0] = (int)sv.x; s[1] = (int)sv.y; s[2] = (int)sv.z; s[3] = (int)sv.w;
        d[0] = (int)dv.x; d[1] = (int)dv.y; d[2] = (int)dv.z; d[3] = (int)dv.w;
    } else {
        int4 sv = *(const int4*)((const int*)ei + e0);
        int4 dv = *(const int4*)((const int*)ei + E + e0);
        s[0] = sv.x; s[1] = sv.y; s[2] = sv.z; s[3] = sv.w;
        d[0] = dv.x; d[1] = dv.y; d[2] = dv.z; d[3] = dv.w;
    }
}

// ================= kernel 1: y1 GEMM via tf32 WMMA + zero + dtype detect ======
// 128 threads = 4 warps; each warp computes a 16-node x 32-output tile of
// y1 = x @ W1_l.T with m16n16k8 tf32 MMA. A (x) read directly from global
// (row-major, ld=128); B read in place from W1_l (col-major view: element
// (k,n) = Wl[n*128+k]); acc staged via smem, stored as bf16.
__global__ void __launch_bounds__(128) k_pre(const float* __restrict__ x,
                                             const float* __restrict__ Wl,
                                             const unsigned int* __restrict__ ei32,
                                             int n) {
    // dtype detect (block 0): ids < 2^31 => int64 storage has odd words == 0
    if (blockIdx.x == 0) {
        __shared__ int found;
        if (threadIdx.x == 0) found = 0;
        __syncthreads();
        for (int i = 1 + 2 * threadIdx.x; i < 4096; i += 2 * blockDim.x)
            if (ei32[i] != 0u) found = 1;  // benign race
        __syncthreads();
        if (threadIdx.x == 0) g_is64 = (found == 0) ? 1 : 0;
    }
    // zero scratch
    {
        int gtid = blockIdx.x * blockDim.x + threadIdx.x;
        int stride = gridDim.x * blockDim.x;
        unsigned int* a32 = (unsigned int*)g_agg1b;
        int tot = n * HID / 2;
        for (int i = gtid; i < tot; i += stride) a32[i] = 0u;
        for (int i = gtid; i < n; i += stride) {
            g_deg[i] = 0.0f;
            g_agg2[i] = 0.0f;
        }
    }

    __shared__ __align__(16) float sstage[4][16 * 32];   // 8 KB

    int warp = threadIdx.x >> 5;
    int lane = threadIdx.x & 31;
    int ntiles = n >> 4;                                  // full 16-node tiles

    for (int tile = blockIdx.x * 4 + warp; tile < ntiles; tile += gridDim.x * 4) {
        int m0 = tile * 16;

        wmma::fragment<wmma::matrix_a, 16, 16, 8, wmma::precision::tf32,
                       wmma::row_major> fa;
        wmma::fragment<wmma::matrix_b, 16, 16, 8, wmma::precision::tf32,
                       wmma::col_major> fb0, fb1;
        wmma::fragment<wmma::accumulator, 16, 16, 8, float> acc0, acc1;
        wmma::fill_fragment(acc0, 0.0f);
        wmma::fill_fragment(acc1, 0.0f);

#pragma unroll
        for (int k0 = 0; k0 < DIN; k0 += 8) {
            wmma::load_matrix_sync(fa, x + (long)m0 * DIN + k0, DIN);
#pragma unroll
            for (int i = 0; i < fa.num_elements; i++)
                fa.x[i] = wmma::__float_to_tf32(fa.x[i]);
            wmma::load_matrix_sync(fb0, Wl + k0, DIN);            // n 0..15
            wmma::load_matrix_sync(fb1, Wl + 16 * DIN + k0, DIN); // n 16..31
#pragma unroll
            for (int i = 0; i < fb0.num_elements; i++) {
                fb0.x[i] = wmma::__float_to_tf32(fb0.x[i]);
                fb1.x[i] = wmma::__float_to_tf32(fb1.x[i]);
            }
            wmma::mma_sync(acc0, fa, fb0, acc0);
            wmma::mma_sync(acc1, fa, fb1, acc1);
        }

        wmma::store_matrix_sync(&sstage[warp][0], acc0, 32, wmma::mem_row_major);
        wmma::store_matrix_sync(&sstage[warp][16], acc1, 32, wmma::mem_row_major);
        __syncwarp();

        // 16 rows x 16 bf162 pairs = 256 stores spread over 32 lanes
        __nv_bfloat162* y2 = (__nv_bfloat162*)g_y1b;
#pragma unroll
        for (int idx = lane; idx < 256; idx += 32) {
            int row = idx >> 4, cp = idx & 15;
            float f0 = sstage[warp][row * 32 + cp * 2];
            float f1 = sstage[warp][row * 32 + cp * 2 + 1];
            y2[(m0 + row) * 16 + cp] = __floats2bfloat162_rn(f0, f1);
        }
        __syncwarp();
    }

    // tail nodes (n % 16): scalar path, block 0 warp 0
    if (blockIdx.x == 0 && warp == 0) {
        for (int node = ntiles * 16; node < n; node++) {
            int o = lane;                      // 32 outputs, one per lane
            const float4* xr = (const float4*)(x + (long)node * DIN);
            const float4* wr = (const float4*)(Wl + o * DIN);
            float s = 0.0f;
#pragma unroll
            for (int j = 0; j < 32; j++) {
                float4 a = xr[j], w = wr[j];
                s += a.x * w.x + a.y * w.y + a.z * w.z + a.w * w.w;
            }
            g_y1b[node * 32 + o] = __float2bfloat16(s);
        }
    }
}

// ================= kernel 2 (fat): r1 GEMM blocks + layer-1 edge scatter ======
#define NB 8
#define GB 444
__global__ void __launch_bounds__(256) k_fat(const float* __restrict__ x,
                                             const float* __restrict__ Wr,
                                             const void* __restrict__ ei,
                                             int n, int E) {
    if (blockIdx.x < GB) {
        // ---------------- r1 GEMM role ----------------
        __shared__ __align__(16) float sx[NB * DIN];
        __shared__ float sp[3 * NB * 32];

        int t = threadIdx.x;
        int o = t & 31;
        int h = (t >> 5) & 3;
        int sg = t >> 7;

        const float* wrow = Wr + o * DIN + h * 32;
        ulonglong2 wreg[8];
#pragma unroll
        for (int j = 0; j < 8; j++)
            wreg[j] = ((const ulonglong2*)wrow)[j];

        const float4* x4 = (const float4*)x;
        int nbatch = (n + NB - 1) / NB;

        for (int b = blockIdx.x; b < nbatch; b += GB) {
            int nb0 = b * NB;
            {
                int idx = t;
                int nn = idx >> 5, k4 = idx & 31;
                float4 v = make_float4(0.f, 0.f, 0.f, 0.f);
                if (nb0 + nn < n) v = x4[(nb0 + nn) * 32 + k4];
                ((float4*)sx)[idx] = v;
            }
            __syncthreads();

            float sum[NB / 2];
#pragma unroll
            for (int i = 0; i < NB / 2; i++) {
                int nn = sg + 2 * i;
                const ulonglong2* xp = (const ulonglong2*)(sx + nn * DIN + h * 32);
                unsigned long long aA = 0ull, aB = 0ull;
#pragma unroll
                for (int j = 0; j < 8; j++) {
                    ulonglong2 xv = xp[j];
                    aA = fma2(xv.x, wreg[j].x, aA);
                    aB = fma2(xv.y, wreg[j].y, aB);
                }
                sum[i] = hsum2(aA) + hsum2(aB);
            }
            if (h > 0) {
#pragma unroll
                for (int i = 0; i < NB / 2; i++) {
                    int nn = sg + 2 * i;
                    sp[(h - 1) * (NB * 32) + nn * 32 + o] = sum[i];
                }
            }
            __syncthreads();
            if (h == 0) {
#pragma unroll
                for (int i = 0; i < NB / 2; i++) {
                    int nn = sg + 2 * i;
                    int node = nb0 + nn;
                    if (node < n) {
                        float v = sum[i] + sp[nn * 32 + o]
                                + sp[NB * 32 + nn * 32 + o]
                                + sp[2 * NB * 32 + nn * 32 + o];
                        g_r1[node * 32 + o] = v;
                    }
                }
            }
        }
    } else {
        // ---------------- edge-scatter role ----------------
        int is64 = g_is64;
        int ngroups = E >> 2;
        int t = (blockIdx.x - GB) * 256 + threadIdx.x;
        int g = t >> 2, c = t & 3;

        const uint4* y4 = (const uint4*)g_y1b;
        char* aggb = (char*)g_agg1b;

        if (g < ngroups) {
            int e0 = g * 4;
            int s[4], d[4];
            load_edges4(ei, E, e0, is64, s, d);
            uint4 v[4];
#pragma unroll
            for (int i = 0; i < 4; i++)
                v[i] = y4[s[i] * 4 + c];
#pragma unroll
            for (int i = 0; i < 4; i++)
                red_add_bf16x8(aggb + d[i] * 64 + c * 16, v[i]);
            if (c == 0) {
#pragma unroll
                for (int i = 0; i < 4; i++)
                    atomicAdd(&g_deg[d[i]], 1.0f);
            }
        } else if (g == ngroups) {
            for (int e = ngroups * 4; e < E; e++) {
                int s = is64 ? (int)((const long long*)ei)[e] : ((const int*)ei)[e];
                int d = is64 ? (int)((const long long*)ei)[E + e] : ((const int*)ei)[E + e];
                uint4 v = y4[s * 4 + c];
                red_add_bf16x8(aggb + d * 64 + c * 16, v);
                if (c == 0) atomicAdd(&g_deg[d], 1.0f);
            }
        }
    }
}

// ================= kernel 3: node update + scalar layer-2 projections =========
__global__ void __launch_bounds__(256) k_node1(const float* __restrict__ b1,
                                               const float* __restrict__ W2l,
                                               const float* __restrict__ W2r,
                                               int n) {
    int t = blockIdx.x * blockDim.x + threadIdx.x;
    int node = t >> 3, c = t & 7;
    if (node >= n) return;
    float invd = 1.0f / fmaxf(g_deg[node], 1.0f);
    uint2 ab = ((const uint2*)g_agg1b)[node * 8 + c];
    float2 a0 = __bfloat1622float2(*(__nv_bfloat162*)&ab.x);
    float2 a1 = __bfloat1622float2(*(__nv_bfloat162*)&ab.y);
    float4 r = ((const float4*)g_r1)[node * 8 + c];
    float4 bb = ((const float4*)b1)[c];
    float4 h;
    h.x = fmaxf(fmaf(a0.x, invd, bb.x + r.x), 0.0f);
    h.y = fmaxf(fmaf(a0.y, invd, bb.y + r.y), 0.0f);
    h.z = fmaxf(fmaf(a1.x, invd, bb.z + r.z), 0.0f);
    h.w = fmaxf(fmaf(a1.y, invd, bb.w + r.w), 0.0f);
    float4 wl = ((const float4*)W2l)[c];
    float4 wr = ((const float4*)W2r)[c];
    float zl = h.x * wl.x + h.y * wl.y + h.z * wl.z + h.w * wl.w;
    float zr = h.x * wr.x + h.y * wr.y + h.z * wr.z + h.w * wr.w;
#pragma unroll
    for (int o = 1; o <= 4; o <<= 1) {
        zl += __shfl_xor_sync(0xFFFFFFFFu, zl, o);
        zr += __shfl_xor_sync(0xFFFFFFFFu, zr, o);
    }
    if (c == 0) {
        g_z2[node] = zl;
        g_r2[node] = zr;
    }
}

// ================= kernel 4: layer-2 scalar edge scatter ======================
__global__ void __launch_bounds__(256) k_edge2(const void* __restrict__ ei, int E) {
    int is64 = g_is64;
    int ngroups = E >> 2;
    int g = blockIdx.x * blockDim.x + threadIdx.x;
    if (g < ngroups) {
        int e0 = g * 4;
        int s[4], d[4];
        load_edges4(ei, E, e0, is64, s, d);
        float z[4];
#pragma unroll
        for (int i = 0; i < 4; i++) z[i] = g_z2[s[i]];
#pragma unroll
        for (int i = 0; i < 4; i++) atomicAdd(&g_agg2[d[i]], z[i]);
    } else if (g == ngroups) {
        for (int e = ngroups * 4; e < E; e++) {
            int s = is64 ? (int)((const long long*)ei)[e] : ((const int*)ei)[e];
            int d = is64 ? (int)((const long long*)ei)[E + e] : ((const int*)ei)[E + e];
            atomicAdd(&g_agg2[d], g_z2[s]);
        }
    }
}

// ================= kernel 5: final sigmoid ============
__global__ void k_out(float* __restrict__ out, const float* __restrict__ b2, int n) {
    int i = blockIdx.x * blockDim.x + threadIdx.x;
    if (i < n) {
        float inv = 1.0f / fmaxf(g_deg[i], 1.0f);
        float v = fmaf(g_agg2[i], inv, b2[0] + g_r2[i]);
        out[i] = 1.0f / (1.0f + expf(-v));
    }
}

// ---------------- launch ----------------
extern "C" void kernel_launch(void* const* d_in, const int* in_sizes, int n_in,
                              void* d_out, int out_size) {
    const float* x   = (const float*)d_in[0];
    const void*  ei  = d_in[1];
    const float* W1l = (const float*)d_in[2];
    const float* b1  = (const float*)d_in[3];
    const float* W1r = (const float*)d_in[4];
    const float* W2l = (const float*)d_in[5];
    const float* b2  = (const float*)d_in[6];
    const float* W2r = (const float*)d_in[7];
    float* out = (float*)d_out;

    int n = in_sizes[0] / DIN;
    int E = in_sizes[1] / 2;
    if (n > NMAX) n = NMAX;
    if (E > EMAX) E = EMAX;

    int ntiles = n >> 4;
    int preblocks = (ntiles + 3) / 4;
    if (preblocks < 148) preblocks = 148;
    k_pre<<<preblocks, 128>>>(x, W1l, (const unsigned int*)ei, n);
    int edge_blocks = (E + 4 + 255) / 256;
    k_fat<<<GB + edge_blocks, 256>>>(x, W1r, ei, n, E);
    k_node1<<<(n * 8 + 255) / 256, 256>>>(b1, W2l, W2r, n);
    int ng = (E >> 2) + 1;
    k_edge2<<<(ng + 255) / 256, 256>>>(ei, E);
    k_out<<<(n + 255) / 256, 256>>>(out, b2, n);
}

// round 13
// speedup vs baseline: 1.0041x; 1.0041x over previous
#include <cuda_runtime.h>
#include <cuda_bf16.h>
#include <mma.h>
#include <math.h>

using namespace nvcuda;

#define NMAX 50000
#define EMAX 800000
#define HID  32
#define DIN  128

// ---------------- scratch (static; no cudaMalloc allowed) ----------------
__device__ __align__(128) __nv_bfloat16 g_y1b[NMAX * HID];   // x @ W1_l.T (bf16)
__device__ __align__(128) __nv_bfloat16 g_agg1b[NMAX * HID]; // bf16 edge sums
__device__ __align__(128) float g_r1[NMAX * HID];            // x @ W1_r.T (fp32)
__device__ __align__(128) float g_deg[NMAX];
__device__ __align__(128) float g_z2[NMAX];
__device__ __align__(128) float g_r2[NMAX];
__device__ __align__(128) float g_agg2[NMAX];
__device__ int g_is64;

// ---------------- helpers ----------------
// 16-byte reduction of 8 bf16 values
__device__ __forceinline__ void red_add_bf16x8(void* addr, uint4 v) {
#if !defined(__CUDA_ARCH__) || __CUDA_ARCH__ >= 900
    asm volatile("red.global.add.noftz.v4.bf16x2 [%0], {%1, %2, %3, %4};"
                 :: "l"(addr), "r"(v.x), "r"(v.y), "r"(v.z), "r"(v.w)
                 : "memory");
#else
    __nv_bfloat162* p = (__nv_bfloat162*)addr;
    atomicAdd(p + 0, *(__nv_bfloat162*)&v.x);
    atomicAdd(p + 1, *(__nv_bfloat162*)&v.y);
    atomicAdd(p + 2, *(__nv_bfloat162*)&v.z);
    atomicAdd(p + 3, *(__nv_bfloat162*)&v.w);
#endif
}
__device__ __forceinline__ void load_edges4(const void* ei, int E, int e0,
                                            int is64, int* s, int* d) {
    if (is64) {
        longlong4 sv = *(const longlong4*)((const long long*)ei + e0);
        longlong4 dv = *(const longlong4*)((const long long*)ei + E + e0);
        s[0] = (int)sv.x; s[1] = (int)sv.y; s[2] = (int)sv.z; s[3] = (int)sv.w;
        d[0] = (int)dv.x; d[1] = (int)dv.y; d[2] = (int)dv.z; d[3] = (int)dv.w;
    } else {
        int4 sv = *(const int4*)((const int*)ei + e0);
        int4 dv = *(const int4*)((const int*)ei + E + e0);
        s[0] = sv.x; s[1] = sv.y; s[2] = sv.z; s[3] = sv.w;
        d[0] = dv.x; d[1] = dv.y; d[2] = dv.z; d[3] = dv.w;
    }
}

// ================= kernel 1: BOTH projections via tf32 WMMA, x read once ======
// 128 threads = 4 warps. Block processes a 64-node super-tile: cooperative
// 32KB smem load of x (coalesced float4, high MLP), then warp w computes the
// 16-node slice [w*16, w*16+16) for both y1 = x@W1_l.T (bf16 out) and
// r1 = x@W1_r.T (fp32 out) with m16n16k8 tf32 MMA. B fragments read in place
// from Wl/Wr (col-major view, ld=DIN; 32KB total, L1-resident).
__global__ void __launch_bounds__(128) k_pre(const float* __restrict__ x,
                                             const float* __restrict__ Wl,
                                             const float* __restrict__ Wr,
                                             const unsigned int* __restrict__ ei32,
                                             int n) {
    // dtype detect (block 0): ids < 2^31 => int64 storage has odd words == 0
    if (blockIdx.x == 0) {
        __shared__ int found;
        if (threadIdx.x == 0) found = 0;
        __syncthreads();
        for (int i = 1 + 2 * threadIdx.x; i < 4096; i += 2 * blockDim.x)
            if (ei32[i] != 0u) found = 1;  // benign race
        __syncthreads();
        if (threadIdx.x == 0) g_is64 = (found == 0) ? 1 : 0;
    }
    // zero scratch
    {
        int gtid = blockIdx.x * blockDim.x + threadIdx.x;
        int stride = gridDim.x * blockDim.x;
        unsigned int* a32 = (unsigned int*)g_agg1b;
        int tot = n * HID / 2;
        for (int i = gtid; i < tot; i += stride) a32[i] = 0u;
        for (int i = gtid; i < n; i += stride) {
            g_deg[i] = 0.0f;
            g_agg2[i] = 0.0f;
        }
    }

    __shared__ __align__(16) float sx[64 * DIN];       // 32 KB

    int t = threadIdx.x;
    int warp = t >> 5;
    int lane = t & 31;
    int ntile16 = (n + 15) >> 4;
    int nsuper = (ntile16 + 3) >> 2;
    const float4* x4 = (const float4*)x;

    for (int st = blockIdx.x; st < nsuper; st += gridDim.x) {
        int base = st * 64;
        // cooperative x load: 64 nodes x 32 float4 = 2048 float4, 16/thread
#pragma unroll
        for (int i = 0; i < 16; i++) {
            int idx = t + i * 128;
            int node = base + (idx >> 5), k4 = idx & 31;
            float4 v = make_float4(0.f, 0.f, 0.f, 0.f);
            if (node < n) v = x4[node * 32 + k4];
            ((float4*)sx)[idx] = v;
        }
        __syncthreads();

        int tile = st * 4 + warp;
        wmma::fragment<wmma::accumulator, 16, 16, 8, float> accl0, accl1, accr0, accr1;
        if (tile < ntile16) {
            wmma::fragment<wmma::matrix_a, 16, 16, 8, wmma::precision::tf32,
                           wmma::row_major> fa;
            wmma::fragment<wmma::matrix_b, 16, 16, 8, wmma::precision::tf32,
                           wmma::col_major> fb;
            wmma::fill_fragment(accl0, 0.0f);
            wmma::fill_fragment(accl1, 0.0f);
            wmma::fill_fragment(accr0, 0.0f);
            wmma::fill_fragment(accr1, 0.0f);

#pragma unroll
            for (int k0 = 0; k0 < DIN; k0 += 8) {
                wmma::load_matrix_sync(fa, sx + warp * 16 * DIN + k0, DIN);
#pragma unroll
                for (int i = 0; i < fa.num_elements; i++)
                    fa.x[i] = wmma::__float_to_tf32(fa.x[i]);

                wmma::load_matrix_sync(fb, Wl + k0, DIN);            // out 0..15
#pragma unroll
                for (int i = 0; i < fb.num_elements; i++)
                    fb.x[i] = wmma::__float_to_tf32(fb.x[i]);
                wmma::mma_sync(accl0, fa, fb, accl0);

                wmma::load_matrix_sync(fb, Wl + 16 * DIN + k0, DIN); // out 16..31
#pragma unroll
                for (int i = 0; i < fb.num_elements; i++)
                    fb.x[i] = wmma::__float_to_tf32(fb.x[i]);
                wmma::mma_sync(accl1, fa, fb, accl1);

                wmma::load_matrix_sync(fb, Wr + k0, DIN);
#pragma unroll
                for (int i = 0; i < fb.num_elements; i++)
                    fb.x[i] = wmma::__float_to_tf32(fb.x[i]);
                wmma::mma_sync(accr0, fa, fb, accr0);

                wmma::load_matrix_sync(fb, Wr + 16 * DIN + k0, DIN);
#pragma unroll
                for (int i = 0; i < fb.num_elements; i++)
                    fb.x[i] = wmma::__float_to_tf32(fb.x[i]);
                wmma::mma_sync(accr1, fa, fb, accr1);
            }

            // r1: store fp32 directly to global (row-major, ld=32)
            int m0 = tile * 16;
            wmma::store_matrix_sync(g_r1 + m0 * 32, accr0, 32, wmma::mem_row_major);
            wmma::store_matrix_sync(g_r1 + m0 * 32 + 16, accr1, 32, wmma::mem_row_major);
        }

        __syncthreads();   // x tile dead; reuse sx as y1 staging
        if (tile < ntile16) {
            float* stg = sx + warp * 512;               // 16 x 32 floats
            wmma::store_matrix_sync(stg, accl0, 32, wmma::mem_row_major);
            wmma::store_matrix_sync(stg + 16, accl1, 32, wmma::mem_row_major);
            __syncwarp();
            int m0 = tile * 16;
            __nv_bfloat162* y2 = (__nv_bfloat162*)g_y1b;
#pragma unroll
            for (int idx = lane; idx < 256; idx += 32) {
                int row = idx >> 4, cp = idx & 15;
                float f0 = stg[row * 32 + cp * 2];
                float f1 = stg[row * 32 + cp * 2 + 1];
                y2[(m0 + row) * 16 + cp] = __floats2bfloat162_rn(f0, f1);
            }
        }
        __syncthreads();
    }
}

// ================= kernel 2: layer-1 edge scatter (bf16 payload) ==============
__global__ void __launch_bounds__(256) k_edge1(const void* __restrict__ ei, int E) {
    int is64 = g_is64;
    int ngroups = E >> 2;
    int t = blockIdx.x * blockDim.x + threadIdx.x;
    int g = t >> 2, c = t & 3;

    const uint4* y4 = (const uint4*)g_y1b;
    char* aggb = (char*)g_agg1b;

    if (g < ngroups) {
        int e0 = g * 4;
        int s[4], d[4];
        load_edges4(ei, E, e0, is64, s, d);
        uint4 v[4];
#pragma unroll
        for (int i = 0; i < 4; i++)
            v[i] = y4[s[i] * 4 + c];
#pragma unroll
        for (int i = 0; i < 4; i++)
            red_add_bf16x8(aggb + d[i] * 64 + c * 16, v[i]);
        if (c == 0) {
#pragma unroll
            for (int i = 0; i < 4; i++)
                atomicAdd(&g_deg[d[i]], 1.0f);
        }
    } else if (g == ngroups) {  // tail (E % 4)
        for (int e = ngroups * 4; e < E; e++) {
            int s = is64 ? (int)((const long long*)ei)[e] : ((const int*)ei)[e];
            int d = is64 ? (int)((const long long*)ei)[E + e] : ((const int*)ei)[E + e];
            uint4 v = y4[s * 4 + c];
            red_add_bf16x8(aggb + d * 64 + c * 16, v);
            if (c == 0) atomicAdd(&g_deg[d], 1.0f);
        }
    }
}

// ================= kernel 3: node update + scalar layer-2 projections =========
__global__ void __launch_bounds__(256) k_node1(const float* __restrict__ b1,
                                               const float* __restrict__ W2l,
                                               const float* __restrict__ W2r,
                                               int n) {
    int t = blockIdx.x * blockDim.x + threadIdx.x;
    int node = t >> 3, c = t & 7;
    if (node >= n) return;
    float invd = 1.0f / fmaxf(g_deg[node], 1.0f);
    uint2 ab = ((const uint2*)g_agg1b)[node * 8 + c];
    float2 a0 = __bfloat1622float2(*(__nv_bfloat162*)&ab.x);
    float2 a1 = __bfloat1622float2(*(__nv_bfloat162*)&ab.y);
    float4 r = ((const float4*)g_r1)[node * 8 + c];
    float4 bb = ((const float4*)b1)[c];
    float4 h;
    h.x = fmaxf(fmaf(a0.x, invd, bb.x + r.x), 0.0f);
    h.y = fmaxf(fmaf(a0.y, invd, bb.y + r.y), 0.0f);
    h.z = fmaxf(fmaf(a1.x, invd, bb.z + r.z), 0.0f);
    h.w = fmaxf(fmaf(a1.y, invd, bb.w + r.w), 0.0f);
    float4 wl = ((const float4*)W2l)[c];
    float4 wr = ((const float4*)W2r)[c];
    float zl = h.x * wl.x + h.y * wl.y + h.z * wl.z + h.w * wl.w;
    float zr = h.x * wr.x + h.y * wr.y + h.z * wr.z + h.w * wr.w;
#pragma unroll
    for (int o = 1; o <= 4; o <<= 1) {
        zl += __shfl_xor_sync(0xFFFFFFFFu, zl, o);
        zr += __shfl_xor_sync(0xFFFFFFFFu, zr, o);
    }
    if (c == 0) {
        g_z2[node] = zl;
        g_r2[node] = zr;
    }
}

// ================= kernel 4: layer-2 scalar edge scatter ======================
__global__ void __launch_bounds__(256) k_edge2(const void* __restrict__ ei, int E) {
    int is64 = g_is64;
    int ngroups = E >> 2;
    int g = blockIdx.x * blockDim.x + threadIdx.x;
    if (g < ngroups) {
        int e0 = g * 4;
        int s[4], d[4];
        load_edges4(ei, E, e0, is64, s, d);
        float z[4];
#pragma unroll
        for (int i = 0; i < 4; i++) z[i] = g_z2[s[i]];
#pragma unroll
        for (int i = 0; i < 4; i++) atomicAdd(&g_agg2[d[i]], z[i]);
    } else if (g == ngroups) {
        for (int e = ngroups * 4; e < E; e++) {
            int s = is64 ? (int)((const long long*)ei)[e] : ((const int*)ei)[e];
            int d = is64 ? (int)((const long long*)ei)[E + e] : ((const int*)ei)[E + e];
            atomicAdd(&g_agg2[d], g_z2[s]);
        }
    }
}

// ================= kernel 5: final sigmoid ============
__global__ void k_out(float* __restrict__ out, const float* __restrict__ b2, int n) {
    int i = blockIdx.x * blockDim.x + threadIdx.x;
    if (i < n) {
        float inv = 1.0f / fmaxf(g_deg[i], 1.0f);
        float v = fmaf(g_agg2[i], inv, b2[0] + g_r2[i]);
        out[i] = 1.0f / (1.0f + expf(-v));
    }
}

// ---------------- launch ----------------
extern "C" void kernel_launch(void* const* d_in, const int* in_sizes, int n_in,
                              void* d_out, int out_size) {
    const float* x   = (const float*)d_in[0];
    const void*  ei  = d_in[1];
    const float* W1l = (const float*)d_in[2];
    const float* b1  = (const float*)d_in[3];
    const float* W1r = (const float*)d_in[4];
    const float* W2l = (const float*)d_in[5];
    const float* b2  = (const float*)d_in[6];
    const float* W2r = (const float*)d_in[7];
    float* out = (float*)d_out;

    int n = in_sizes[0] / DIN;
    int E = in_sizes[1] / 2;
    if (n > NMAX) n = NMAX;
    if (E > EMAX) E = EMAX;

    int ntile16 = (n + 15) >> 4;
    int nsuper = (ntile16 + 3) >> 2;
    k_pre<<<nsuper, 128>>>(x, W1l, W1r, (const unsigned int*)ei, n);
    int edge_blocks = (E + 4 + 255) / 256;
    k_edge1<<<edge_blocks, 256>>>(ei, E);
    k_node1<<<(n * 8 + 255) / 256, 256>>>(b1, W2l, W2r, n);
    int ng = (E >> 2) + 1;
    k_edge2<<<(ng + 255) / 256, 256>>>(ei, E);
    k_out<<<(n + 255) / 256, 256>>>(out, b2, n);
}